// round 12
// baseline (speedup 1.0000x reference)
#include <cuda_runtime.h>
#include <cuda_bf16.h>

// LocalFeatureAggregation: B=4, N=16384, K=16, C=64, D=64
// out[b,n,0:64]   = mean_k leakyrelu(geom[b,n,k,:] @ w[d,:] + b[d])
// out[b,n,64:128] = mean_k features[b, idx[b,n,k], :]
//
// R12 (= R7 resubmit; five broker timeouts in a row, kernel has never run):
// channel-pair f32x2 packing (weights = 5 u64), geom broadcast pairs
// pre-DUPLICATED in shared ({x,x,y,y,z,z,w,w}) so the loop has zero packing
// MOVs, 32-bit byte-offset gather addressing, launch_bounds(128,10).

#define BN      65536
#define NPTS    16384
#define KNB     16
#define CH      64
#define PTS_PER_BLK 4
#define NTHREADS 128

typedef unsigned long long u64;

__device__ __forceinline__ u64 pack2(float lo, float hi) {
    u64 r; asm("mov.b64 %0, {%1, %2};" : "=l"(r) : "f"(lo), "f"(hi)); return r;
}
__device__ __forceinline__ u64 bcast2(float v) {
    u64 r; asm("mov.b64 %0, {%1, %1};" : "=l"(r) : "f"(v)); return r;
}
__device__ __forceinline__ u64 fma2(u64 a, u64 b, u64 c) {
    u64 d; asm("fma.rn.f32x2 %0, %1, %2, %3;" : "=l"(d) : "l"(a), "l"(b), "l"(c)); return d;
}
__device__ __forceinline__ u64 add2(u64 a, u64 b) {
    u64 d; asm("add.rn.f32x2 %0, %1, %2;" : "=l"(d) : "l"(a), "l"(b)); return d;
}
__device__ __forceinline__ u64 mul2(u64 a, u64 b) {
    u64 d; asm("mul.rn.f32x2 %0, %1, %2;" : "=l"(d) : "l"(a), "l"(b)); return d;
}
__device__ __forceinline__ u64 abs2(u64 a) {
    u64 d; asm("and.b64 %0, %1, 0x7FFFFFFF7FFFFFFF;" : "=l"(d) : "l"(a)); return d;
}

__global__ __launch_bounds__(NTHREADS, 10)
void lfa_kernel(const float* __restrict__ features,      // [B,N,64]
                const float* __restrict__ geom,          // [B,N,16,4]
                const float* __restrict__ w,             // [64,4]
                const float* __restrict__ bias,          // [64]
                const int* __restrict__ nbr,             // [B,N,16] int32
                float* __restrict__ out)                 // [B,N,128]
{
    // Duplicated geom: sg2[pt][k][.] = {x,x, y,y, z,z, w,w}  (32B per (pt,k))
    __shared__ __align__(16) float    sg2[PTS_PER_BLK][KNB][8];
    __shared__ __align__(4)  unsigned soff[PTS_PER_BLK][KNB];   // idx*256 byte offsets

    const int tid = threadIdx.x;
    const long long blk_base = (long long)blockIdx.x * PTS_PER_BLK;

    // Stage: threads 0..63 duplicate geom (one (pt,k) each),
    //        threads 64..127 load + pre-scale the 64 neighbor indices.
    if (tid < 64) {
        const int spt = tid >> 4, k = tid & 15;
        const float4 gq = ((const float4*)geom)[blk_base * KNB + tid];
        float4* dst = (float4*)&sg2[spt][k][0];
        dst[0] = make_float4(gq.x, gq.x, gq.y, gq.y);
        dst[1] = make_float4(gq.z, gq.z, gq.w, gq.w);
    } else {
        const int t = tid - 64;
        ((unsigned*)soff)[t] = ((unsigned)nbr[blk_base * KNB + t]) << 8;  // *256B/row
    }
    __syncthreads();

    const int lane = tid & 31;          // channel pair: channels 2*lane, 2*lane+1
    const int pt   = tid >> 5;          // warp = point
    const long long g = blk_base + pt;
    const int b = (int)(g >> 14);       // g / N

    // Channel-pair packed weights: 5 u64 total
    const float4 wa = ((const float4*)w)[lane * 2 + 0];   // channel c0 row
    const float4 wb = ((const float4*)w)[lane * 2 + 1];   // channel c1 row
    const float2 bf = ((const float2*)bias)[lane];
    const u64 wx = pack2(wa.x, wb.x);
    const u64 wy = pack2(wa.y, wb.y);
    const u64 wz = pack2(wa.z, wb.z);
    const u64 ww = pack2(wa.w, wb.w);
    const u64 bb = pack2(bf.x, bf.y);
    const u64 C055 = bcast2(0.55f), C045 = bcast2(0.45f);

    u64 tacc  = 0;            // (sum_t c0, sum_t c1)
    u64 facc0 = 0, facc1 = 0; // split f accumulators for ILP

    // Warp-uniform gather base (b is warp-uniform) + per-lane byte offset
    const char* fbc = (const char*)features + (size_t)b * (NPTS * CH * 4);
    const unsigned laneoff = (unsigned)lane * 8u;

    #pragma unroll
    for (int k = 0; k < KNB; k++) {
        // packed geom broadcasts straight from shared
        const ulonglong2 pxy = *((const ulonglong2*)&sg2[pt][k][0]); // (xx, yy)
        const ulonglong2 pzw = *((const ulonglong2*)&sg2[pt][k][4]); // (zz, ww)

        u64 v = fma2(pxy.x, wx, fma2(pxy.y, wy, fma2(pzw.x, wz, fma2(pzw.y, ww, bb))));
        tacc = fma2(v, C055, fma2(abs2(v), C045, tacc));

        // gather: uniform base + 32-bit offset
        const unsigned off = soff[pt][k] + laneoff;
        const u64 f = __ldg((const u64*)(fbc + off));
        if (k & 1) facc1 = add2(facc1, f);
        else       facc0 = add2(facc0, f);
    }

    const u64 S = bcast2(1.0f / (float)KNB);
    const u64 tv = mul2(tacc, S);
    const u64 fv = mul2(add2(facc0, facc1), S);

    u64* op = (u64*)(out + g * (2 * CH));
    op[lane]      = tv;   // t channels [2*lane, 2*lane+1]
    op[32 + lane] = fv;   // f channels [64+2*lane, 64+2*lane+1]
}

extern "C" void kernel_launch(void* const* d_in, const int* in_sizes, int n_in,
                              void* d_out, int out_size)
{
    const float* features = (const float*)d_in[0];
    const float* geom     = (const float*)d_in[1];
    const float* w        = (const float*)d_in[2];
    const float* bias     = (const float*)d_in[3];
    const int*   nbr      = (const int*)d_in[4];
    float*       out      = (float*)d_out;

    const int nblocks = BN / PTS_PER_BLK;   // 16384
    lfa_kernel<<<nblocks, NTHREADS>>>(features, geom, w, bias, nbr, out);
}